// round 8
// baseline (speedup 1.0000x reference)
#include <cuda_runtime.h>
#include <math.h>
#include <stdint.h>

#define ND   64
#define ED   32
#define HID  256
#define MSGD 128
#define MAX_EDGES 800000
#define MAX_NODES 50000

#define BM    64      // edge/node/agent tile
#define HPAD  260
#define EPAD  36
#define APAD  68
#define XPAD  132
#define TSTR  68      // transposed-h column stride (floats), 16B multiple
#define PROJW 512     // [Ps(256) | Pr(256)] per node

typedef unsigned long long u64;

// ---- packed f32x2 helpers (sm_103a FFMA2 path) ----
__device__ __forceinline__ u64 ffma2(u64 a, u64 b, u64 c) {
    u64 d;
    asm("fma.rn.f32x2 %0, %1, %2, %3;" : "=l"(d) : "l"(a), "l"(b), "l"(c));
    return d;
}
__device__ __forceinline__ u64 pack2(float x) {
    u64 r;
    asm("mov.b64 %0, {%1, %1};" : "=l"(r) : "f"(x));
    return r;
}
__device__ __forceinline__ float2 unpack2(u64 v) {
    float2 f;
    asm("mov.b64 {%0, %1}, %2;" : "=f"(f.x), "=f"(f.y) : "l"(v));
    return f;
}
__device__ __forceinline__ void red_add_v4(float* p, float4 v) {
    asm volatile("red.global.add.v4.f32 [%0], {%1, %2, %3, %4};"
                 :: "l"(p), "f"(v.x), "f"(v.y), "f"(v.z), "f"(v.w) : "memory");
}

// ---- scratch ----
__device__ int   g_count;
__device__ int   g_active[MAX_EDGES];
__device__ int   g_crecv[MAX_EDGES];
__device__ float g_denom[MAX_NODES];
__device__ float g_aggr[(size_t)MAX_NODES * MSGD];
__device__ float g_proj[(size_t)MAX_NODES * PROJW];
__device__ u64   g_w2dup[(size_t)HID * MSGD];      // (w,w) packed W2

// ---------------- init ----------------
__global__ void init_kernel(int n_agents) {
    int i = blockIdx.x * blockDim.x + threadIdx.x;
    int total = n_agents * MSGD;
    if (i < total) g_aggr[i] = 0.f;
    if (i < n_agents) g_denom[i] = 0.f;
    if (i == 0) g_count = 0;
}

// ---------------- duplicate W2 into packed (w,w) form ------------------------
__global__ void dup_w2_kernel(const float* __restrict__ W2) {
    int i = blockIdx.x * blockDim.x + threadIdx.x;
    if (i < HID * MSGD) {
        unsigned int b = __float_as_uint(W2[i]);
        g_w2dup[i] = ((u64)b << 32) | (u64)b;
    }
}

// ---------------- compact ----------------
__global__ void compact_kernel(const int* __restrict__ recv, int n_edges, int n_agents) {
    int i = blockIdx.x * blockDim.x + threadIdx.x;
    if (i >= n_edges) return;
    int r = recv[i];
    if (r < n_agents) {
        int p = atomicAdd(&g_count, 1);
        g_active[p] = i;
        g_crecv[p]  = r;
    }
}

// ---------------- node projections: P = node_feats @ [W1_s | W1_r] ----------
__global__ __launch_bounds__(256, 2) void node_proj_kernel(
    const float* __restrict__ node_feats, const float* __restrict__ W1,
    int n_nodes, int n_agents)
{
    __shared__ float s_a[BM][APAD];
    const int r0 = blockIdx.x * BM;
    const int by = blockIdx.y;
    const int lim = (by == 0) ? n_nodes : n_agents;
    if (r0 >= lim) return;
    const int tid = threadIdx.x;

    for (int idx = tid; idx < BM * 16; idx += 256) {
        int m = idx >> 4, p = idx & 15;
        int row = r0 + m;
        float4 v = make_float4(0.f, 0.f, 0.f, 0.f);
        if (row < lim) v = ((const float4*)(node_feats + (size_t)row * ND))[p];
        *(float4*)&s_a[m][p * 4] = v;
    }
    __syncthreads();

    const int tx = tid & 31, ty = tid >> 5;
    const int n0 = tx * 8, m0 = ty * 8;
    const float* Wblk = W1 + (size_t)(by * 64) * HID;

    u64 acc[8][4];
    #pragma unroll
    for (int i = 0; i < 8; i++)
        #pragma unroll
        for (int p = 0; p < 4; p++) acc[i][p] = 0ull;

    for (int k = 0; k < 64; k += 4) {
        float av[8][4];
        #pragma unroll
        for (int i = 0; i < 8; i++)
            *(float4*)av[i] = *(const float4*)&s_a[m0 + i][k];
        #pragma unroll
        for (int kk = 0; kk < 4; kk++) {
            const ulonglong2* wp = (const ulonglong2*)(Wblk + (k + kk) * HID + n0);
            ulonglong2 w01 = wp[0], w23 = wp[1];
            u64 w[4] = {w01.x, w01.y, w23.x, w23.y};
            #pragma unroll
            for (int i = 0; i < 8; i++) {
                u64 a = pack2(av[i][kk]);
                #pragma unroll
                for (int p = 0; p < 4; p++) acc[i][p] = ffma2(a, w[p], acc[i][p]);
            }
        }
    }
    #pragma unroll
    for (int i = 0; i < 8; i++) {
        int row = r0 + m0 + i;
        if (row < lim) {
            float* dst = g_proj + (size_t)row * PROJW + by * 256 + n0;
            #pragma unroll
            for (int g = 0; g < 2; g++) {
                float2 u0 = unpack2(acc[i][2 * g]);
                float2 u1 = unpack2(acc[i][2 * g + 1]);
                *(float4*)(dst + g * 4) = make_float4(u0.x, u0.y, u1.x, u1.y);
            }
        }
    }
}

// ---------------- fused edge MLP + softmax-free scatter ----------------------
// 256 threads = 8 warps; tile = 64 edges; 2 blocks/SM.
// h stored TRANSPOSED in smem (s_hT[col][row], rotated for bank spread);
// GEMM2 uses row-pair FFMA2 accumulators: activations load pre-packed from
// s_hT (broadcast LDS.128), weights load pre-duplicated from g_w2dup.
__global__ __launch_bounds__(256, 2) void edge_mlp_kernel(
    const float* __restrict__ edge_feats,
    const float* __restrict__ W1, const float* __restrict__ b1,
    const float* __restrict__ b2,
    const float* __restrict__ w_gate, const float* __restrict__ b_gate,
    const int* __restrict__ senders)
{
    extern __shared__ float smem[];
    float (*s_e)[EPAD] = (float (*)[EPAD])smem;           // 64 x 36
    float* s_hT = smem + BM * EPAD;                        // 256 cols x 68
    int* s_is   = (int*)(s_hT + 256 * TSTR);
    int* s_ir   = s_is + BM;
    int* s_eidx = s_ir + BM;

    const int cnt = g_count;
    const int e0  = blockIdx.x * BM;
    if (e0 >= cnt) return;
    const int tid = threadIdx.x;

    if (tid < BM) {
        int ci = e0 + tid;
        int e = 0, s = 0, r = 0;
        if (ci < cnt) { e = g_active[ci]; s = senders[e]; r = g_crecv[ci]; }
        s_eidx[tid] = e; s_is[tid] = s; s_ir[tid] = r;
    }
    __syncthreads();

    for (int idx = tid; idx < BM * 8; idx += 256) {
        int m = idx >> 3, p = idx & 7;
        float4 v = make_float4(0.f, 0.f, 0.f, 0.f);
        if (e0 + m < cnt) v = ((const float4*)(edge_feats + (size_t)s_eidx[m] * ED))[p];
        *(float4*)&s_e[m][p * 4] = v;
    }
    __syncthreads();

    const int tx = tid & 31, ty = tid >> 5;
    const int n0 = tx * 8, m0 = ty * 8;

    // ---- GEMM1 (edge part, K=32) + bias: per-thread 8 rows x 8 cols ----
    u64 acc[8][4];
    {
        const u64* bp = (const u64*)(b1 + n0);
        u64 bv[4] = {bp[0], bp[1], bp[2], bp[3]};
        #pragma unroll
        for (int i = 0; i < 8; i++)
            #pragma unroll
            for (int p = 0; p < 4; p++) acc[i][p] = bv[p];
    }
    const float* W1e = W1 + (size_t)(2 * ND) * HID;
    for (int k = 0; k < ED; k += 4) {
        float av[8][4];
        #pragma unroll
        for (int i = 0; i < 8; i++)
            *(float4*)av[i] = *(const float4*)&s_e[m0 + i][k];
        #pragma unroll
        for (int kk = 0; kk < 4; kk++) {
            const ulonglong2* wp = (const ulonglong2*)(W1e + (k + kk) * HID + n0);
            ulonglong2 w01 = wp[0], w23 = wp[1];
            u64 w[4] = {w01.x, w01.y, w23.x, w23.y};
            #pragma unroll
            for (int i = 0; i < 8; i++) {
                u64 a = pack2(av[i][kk]);
                #pragma unroll
                for (int p = 0; p < 4; p++) acc[i][p] = ffma2(a, w[p], acc[i][p]);
            }
        }
    }

    // ---- epilogue: add Ps+Pr direct from global, relu, TRANSPOSED store ----
    float hv[8][8];
    #pragma unroll
    for (int i = 0; i < 8; i++) {
        int m = m0 + i;
        const float* ps = g_proj + (size_t)s_is[m] * PROJW + n0;
        const float* pr = g_proj + (size_t)s_ir[m] * PROJW + 256 + n0;
        float4 pa0 = *(const float4*)(ps);
        float4 pa1 = *(const float4*)(ps + 4);
        float4 pb0 = *(const float4*)(pr);
        float4 pb1 = *(const float4*)(pr + 4);
        float2 u0 = unpack2(acc[i][0]), u1 = unpack2(acc[i][1]);
        float2 u2 = unpack2(acc[i][2]), u3 = unpack2(acc[i][3]);
        hv[i][0] = fmaxf(u0.x + pa0.x + pb0.x, 0.f);
        hv[i][1] = fmaxf(u0.y + pa0.y + pb0.y, 0.f);
        hv[i][2] = fmaxf(u1.x + pa0.z + pb0.z, 0.f);
        hv[i][3] = fmaxf(u1.y + pa0.w + pb0.w, 0.f);
        hv[i][4] = fmaxf(u2.x + pa1.x + pb1.x, 0.f);
        hv[i][5] = fmaxf(u2.y + pa1.y + pb1.y, 0.f);
        hv[i][6] = fmaxf(u3.x + pa1.z + pb1.z, 0.f);
        hv[i][7] = fmaxf(u3.y + pa1.w + pb1.w, 0.f);
    }
    {
        int sh = (tx & 7) * 4;                         // ((col>>3)&7)*4, col>>3==tx
        #pragma unroll
        for (int c = 0; c < 8; c++) {
            float* base = s_hT + (n0 + c) * TSTR;
            *(float4*)(base + ((m0 + sh) & 63)) =
                make_float4(hv[0][c], hv[1][c], hv[2][c], hv[3][c]);
            *(float4*)(base + ((m0 + 4 + sh) & 63)) =
                make_float4(hv[4][c], hv[5][c], hv[6][c], hv[7][c]);
        }
    }
    __syncthreads();

    // ---- GEMM2: [64x256] @ [256x128], row-pair acc, per-thread 8 rows x 4 cols
    const int c0 = tx * 4;
    u64 acc2[4][4];
    {
        float4 bb = *(const float4*)(b2 + c0);
        u64 b0 = pack2(bb.x), b1v = pack2(bb.y), b2v = pack2(bb.z), b3v = pack2(bb.w);
        #pragma unroll
        for (int p = 0; p < 4; p++) {
            acc2[p][0] = b0; acc2[p][1] = b1v; acc2[p][2] = b2v; acc2[p][3] = b3v;
        }
    }
    for (int k0 = 0; k0 < HID; k0 += 8) {
        int sh  = ((k0 >> 3) & 7) * 4;
        int ra  = (m0 + sh) & 63;
        int rb  = (m0 + 4 + sh) & 63;
        const float* cb = s_hT + k0 * TSTR;
        const u64* wb = g_w2dup + (size_t)k0 * MSGD + c0;
        #pragma unroll
        for (int kk = 0; kk < 8; kk++) {
            ulonglong2 alo = *(const ulonglong2*)(cb + kk * TSTR + ra);
            ulonglong2 ahi = *(const ulonglong2*)(cb + kk * TSTR + rb);
            u64 a[4] = {alo.x, alo.y, ahi.x, ahi.y};
            const ulonglong2* wd = (const ulonglong2*)(wb + kk * MSGD);
            ulonglong2 w01 = wd[0], w23 = wd[1];
            u64 w[4] = {w01.x, w01.y, w23.x, w23.y};
            #pragma unroll
            for (int p = 0; p < 4; p++) {
                acc2[p][0] = ffma2(a[p], w[0], acc2[p][0]);
                acc2[p][1] = ffma2(a[p], w[1], acc2[p][1]);
                acc2[p][2] = ffma2(a[p], w[2], acc2[p][2]);
                acc2[p][3] = ffma2(a[p], w[3], acc2[p][3]);
            }
        }
    }

    // ---- relu + gate logits (warp reduce) + direct exp-weighted scatter ----
    float wg[4];
    *(float4*)wg = *(const float4*)(w_gate + c0);
    const float bg = b_gate[0];

    float v[8][4], partial[8];
    #pragma unroll
    for (int p = 0; p < 4; p++) {
        #pragma unroll
        for (int c = 0; c < 4; c++) {
            float2 u = unpack2(acc2[p][c]);
            v[2 * p][c]     = fmaxf(u.x, 0.f);
            v[2 * p + 1][c] = fmaxf(u.y, 0.f);
        }
    }
    #pragma unroll
    for (int i = 0; i < 8; i++) {
        float s = v[i][0] * wg[0];
        s = fmaf(v[i][1], wg[1], s);
        s = fmaf(v[i][2], wg[2], s);
        s = fmaf(v[i][3], wg[3], s);
        partial[i] = s;
    }
    #pragma unroll
    for (int o = 16; o >= 1; o >>= 1) {
        #pragma unroll
        for (int i = 0; i < 8; i++)
            partial[i] += __shfl_xor_sync(0xffffffffu, partial[i], o);
    }
    #pragma unroll
    for (int i = 0; i < 8; i++) {
        int ci = e0 + m0 + i;
        if (ci < cnt) {
            float ev = expf(partial[i] + bg);
            int r = s_ir[m0 + i];
            if (tx == 0) atomicAdd(g_denom + r, ev);
            red_add_v4(g_aggr + (size_t)r * MSGD + c0,
                       make_float4(ev * v[i][0], ev * v[i][1], ev * v[i][2], ev * v[i][3]));
        }
    }
}

// ---------------- agent MLP (divides by denom on load) -----------------------
__global__ __launch_bounds__(256, 2) void agent_mlp_kernel(
    const float* __restrict__ W_h1, const float* __restrict__ b_h1,
    const float* __restrict__ W_h2, const float* __restrict__ b_h2,
    const float* __restrict__ W_out, const float* __restrict__ b_out,
    float* __restrict__ out, int n_agents)
{
    extern __shared__ float smem[];
    float (*s_x)[XPAD] = (float (*)[XPAD])smem;
    float (*s_h)[HPAD] = (float (*)[HPAD])(smem + BM * XPAD);

    const int r0 = blockIdx.x * BM;
    const int tid = threadIdx.x;

    for (int idx = tid; idx < BM * 32; idx += 256) {
        int m = idx >> 5, p = idx & 31;
        int r = r0 + m;
        float4 v = make_float4(0.f, 0.f, 0.f, 0.f);
        if (r < n_agents) {
            float inv = __frcp_rn(g_denom[r] + 1e-9f);
            v = *(const float4*)(g_aggr + (size_t)r * MSGD + p * 4);
            v.x *= inv; v.y *= inv; v.z *= inv; v.w *= inv;
        }
        *(float4*)&s_x[m][p * 4] = v;
    }
    __syncthreads();

    const int tx = tid & 31, ty = tid >> 5;
    const int n0 = tx * 8, m0 = ty * 8;

    u64 acc[8][4];
    {
        const u64* bp = (const u64*)(b_h1 + n0);
        u64 bv[4] = {bp[0], bp[1], bp[2], bp[3]};
        #pragma unroll
        for (int i = 0; i < 8; i++)
            #pragma unroll
            for (int p = 0; p < 4; p++) acc[i][p] = bv[p];
    }
    for (int k = 0; k < MSGD; k += 4) {
        float av[8][4];
        #pragma unroll
        for (int i = 0; i < 8; i++)
            *(float4*)av[i] = *(const float4*)&s_x[m0 + i][k];
        #pragma unroll
        for (int kk = 0; kk < 4; kk++) {
            const ulonglong2* wp = (const ulonglong2*)(W_h1 + (k + kk) * HID + n0);
            ulonglong2 w01 = wp[0], w23 = wp[1];
            u64 w[4] = {w01.x, w01.y, w23.x, w23.y};
            #pragma unroll
            for (int i = 0; i < 8; i++) {
                u64 a = pack2(av[i][kk]);
                #pragma unroll
                for (int p = 0; p < 4; p++) acc[i][p] = ffma2(a, w[p], acc[i][p]);
            }
        }
    }
    #pragma unroll
    for (int i = 0; i < 8; i++) {
        #pragma unroll
        for (int g = 0; g < 2; g++) {
            float2 u0 = unpack2(acc[i][2 * g]);
            float2 u1 = unpack2(acc[i][2 * g + 1]);
            float4 r;
            r.x = fmaxf(u0.x, 0.f); r.y = fmaxf(u0.y, 0.f);
            r.z = fmaxf(u1.x, 0.f); r.w = fmaxf(u1.y, 0.f);
            *(float4*)&s_h[m0 + i][n0 + g * 4] = r;
        }
    }
    __syncthreads();

    {
        const u64* bp = (const u64*)(b_h2 + n0);
        u64 bv[4] = {bp[0], bp[1], bp[2], bp[3]};
        #pragma unroll
        for (int i = 0; i < 8; i++)
            #pragma unroll
            for (int p = 0; p < 4; p++) acc[i][p] = bv[p];
    }
    #pragma unroll 2
    for (int k = 0; k < HID; k += 4) {
        float av[8][4];
        #pragma unroll
        for (int i = 0; i < 8; i++)
            *(float4*)av[i] = *(const float4*)&s_h[m0 + i][k];
        #pragma unroll
        for (int kk = 0; kk < 4; kk++) {
            const ulonglong2* wp = (const ulonglong2*)(W_h2 + (k + kk) * HID + n0);
            ulonglong2 w01 = wp[0], w23 = wp[1];
            u64 w[4] = {w01.x, w01.y, w23.x, w23.y};
            #pragma unroll
            for (int i = 0; i < 8; i++) {
                u64 a = pack2(av[i][kk]);
                #pragma unroll
                for (int p = 0; p < 4; p++) acc[i][p] = ffma2(a, w[p], acc[i][p]);
            }
        }
    }

    float wo[8];
    *(float4*)&wo[0] = *(const float4*)(W_out + n0);
    *(float4*)&wo[4] = *(const float4*)(W_out + n0 + 4);
    float partial[8];
    #pragma unroll
    for (int i = 0; i < 8; i++) {
        float s = 0.f;
        #pragma unroll
        for (int p = 0; p < 4; p++) {
            float2 u = unpack2(acc[i][p]);
            s = fmaf(fmaxf(u.x, 0.f), wo[2 * p], s);
            s = fmaf(fmaxf(u.y, 0.f), wo[2 * p + 1], s);
        }
        partial[i] = s;
    }
    #pragma unroll
    for (int o = 16; o >= 1; o >>= 1) {
        #pragma unroll
        for (int i = 0; i < 8; i++)
            partial[i] += __shfl_xor_sync(0xffffffffu, partial[i], o);
    }
    if (tx == 0) {
        float bo = b_out[0];
        #pragma unroll
        for (int i = 0; i < 8; i++) {
            int r = r0 + m0 + i;
            if (r < n_agents) out[r] = tanhf(partial[i] + bo);
        }
    }
}

// ---------------------------------------------------------------------------
extern "C" void kernel_launch(void* const* d_in, const int* in_sizes, int n_in,
                              void* d_out, int out_size) {
    const float* node_feats = (const float*)d_in[0];
    const float* edge_feats = (const float*)d_in[1];
    const float* W_msg1 = (const float*)d_in[2];
    const float* b_msg1 = (const float*)d_in[3];
    const float* W_msg2 = (const float*)d_in[4];
    const float* b_msg2 = (const float*)d_in[5];
    const float* w_gate = (const float*)d_in[6];
    const float* b_gate = (const float*)d_in[7];
    const float* W_h1   = (const float*)d_in[8];
    const float* b_h1   = (const float*)d_in[9];
    const float* W_h2   = (const float*)d_in[10];
    const float* b_h2   = (const float*)d_in[11];
    const float* W_out  = (const float*)d_in[12];
    const float* b_out  = (const float*)d_in[13];
    const int* senders   = (const int*)d_in[14];
    const int* receivers = (const int*)d_in[15];
    float* out = (float*)d_out;

    const int n_edges  = in_sizes[14];
    const int n_nodes  = in_sizes[0] / ND;
    const int n_agents = out_size;

    const int SMEM_EDGE  = (BM * EPAD + 256 * TSTR) * (int)sizeof(float)
                         + 3 * BM * (int)sizeof(int);                       // 79616
    const int SMEM_AGENT = (BM * XPAD + BM * HPAD) * (int)sizeof(float);
    cudaFuncSetAttribute(edge_mlp_kernel, cudaFuncAttributeMaxDynamicSharedMemorySize, SMEM_EDGE);
    cudaFuncSetAttribute(agent_mlp_kernel, cudaFuncAttributeMaxDynamicSharedMemorySize, SMEM_AGENT);

    {
        int total = n_agents * MSGD;
        init_kernel<<<(total + 255) / 256, 256>>>(n_agents);
    }
    dup_w2_kernel<<<(HID * MSGD + 255) / 256, 256>>>(W_msg2);
    compact_kernel<<<(n_edges + 255) / 256, 256>>>(receivers, n_edges, n_agents);
    {
        dim3 grid((n_nodes + BM - 1) / BM, 2);
        node_proj_kernel<<<grid, 256>>>(node_feats, W_msg1, n_nodes, n_agents);
    }
    {
        int grid = (n_edges + BM - 1) / BM;
        edge_mlp_kernel<<<grid, 256, SMEM_EDGE>>>(
            edge_feats, W_msg1, b_msg1, b_msg2, w_gate, b_gate, senders);
    }
    agent_mlp_kernel<<<(n_agents + BM - 1) / BM, 256, SMEM_AGENT>>>(
        W_h1, b_h1, W_h2, b_h2, W_out, b_out, out, n_agents);
}

// round 9
// speedup vs baseline: 1.2808x; 1.2808x over previous
#include <cuda_runtime.h>
#include <math.h>
#include <stdint.h>

#define ND   64
#define ED   32
#define HID  256
#define MSGD 128
#define MAX_EDGES 800000
#define MAX_NODES 50000

#define BM    64      // tile: 64 edges / nodes / agents
#define HPAD  260     // *4B = 1040, 16B multiple
#define EPAD  36
#define APAD  68
#define XPAD  132
#define PROJW 512     // [Ps(256) | Pr(256)] per node

typedef unsigned long long u64;

// ---- packed f32x2 helpers (sm_103a FFMA2 path) ----
__device__ __forceinline__ u64 ffma2(u64 a, u64 b, u64 c) {
    u64 d;
    asm("fma.rn.f32x2 %0, %1, %2, %3;" : "=l"(d) : "l"(a), "l"(b), "l"(c));
    return d;
}
__device__ __forceinline__ u64 pack2(float x) {
    u64 r;
    asm("mov.b64 %0, {%1, %1};" : "=l"(r) : "f"(x));
    return r;
}
__device__ __forceinline__ float2 unpack2(u64 v) {
    float2 f;
    asm("mov.b64 {%0, %1}, %2;" : "=f"(f.x), "=f"(f.y) : "l"(v));
    return f;
}
__device__ __forceinline__ void red_add_v4(float* p, float4 v) {
    asm volatile("red.global.add.v4.f32 [%0], {%1, %2, %3, %4};"
                 :: "l"(p), "f"(v.x), "f"(v.y), "f"(v.z), "f"(v.w) : "memory");
}

// ---- scratch ----
__device__ int   g_count;
__device__ int   g_active[MAX_EDGES];
__device__ int   g_crecv[MAX_EDGES];
__device__ float g_denom[MAX_NODES];
__device__ float g_aggr[(size_t)MAX_NODES * MSGD];
__device__ float g_proj[(size_t)MAX_NODES * PROJW];

// ---------------- init ----------------
__global__ void init_kernel(int n_agents) {
    int i = blockIdx.x * blockDim.x + threadIdx.x;
    int total = n_agents * MSGD;
    if (i < total) g_aggr[i] = 0.f;
    if (i < n_agents) g_denom[i] = 0.f;
    if (i == 0) g_count = 0;
}

// ---------------- compact ----------------
__global__ void compact_kernel(const int* __restrict__ recv, int n_edges, int n_agents) {
    int i = blockIdx.x * blockDim.x + threadIdx.x;
    if (i >= n_edges) return;
    int r = recv[i];
    if (r < n_agents) {
        int p = atomicAdd(&g_count, 1);
        g_active[p] = i;
        g_crecv[p]  = r;
    }
}

// ---------------- node projections: P = node_feats @ [W1_s | W1_r] ----------
__global__ __launch_bounds__(256, 2) void node_proj_kernel(
    const float* __restrict__ node_feats, const float* __restrict__ W1,
    int n_nodes, int n_agents)
{
    __shared__ float s_a[BM][APAD];
    const int r0 = blockIdx.x * BM;
    const int by = blockIdx.y;
    const int lim = (by == 0) ? n_nodes : n_agents;
    if (r0 >= lim) return;
    const int tid = threadIdx.x;

    for (int idx = tid; idx < BM * 16; idx += 256) {
        int m = idx >> 4, p = idx & 15;
        int row = r0 + m;
        float4 v = make_float4(0.f, 0.f, 0.f, 0.f);
        if (row < lim) v = ((const float4*)(node_feats + (size_t)row * ND))[p];
        *(float4*)&s_a[m][p * 4] = v;
    }
    __syncthreads();

    const int tx = tid & 31, ty = tid >> 5;
    const int n0 = tx * 8, m0 = ty * 8;
    const float* Wblk = W1 + (size_t)(by * 64) * HID;

    u64 acc[8][4];
    #pragma unroll
    for (int i = 0; i < 8; i++)
        #pragma unroll
        for (int p = 0; p < 4; p++) acc[i][p] = 0ull;

    for (int k = 0; k < 64; k += 4) {
        float av[8][4];
        #pragma unroll
        for (int i = 0; i < 8; i++)
            *(float4*)av[i] = *(const float4*)&s_a[m0 + i][k];
        #pragma unroll
        for (int kk = 0; kk < 4; kk++) {
            const ulonglong2* wp = (const ulonglong2*)(Wblk + (k + kk) * HID + n0);
            ulonglong2 w01 = wp[0], w23 = wp[1];
            u64 w[4] = {w01.x, w01.y, w23.x, w23.y};
            #pragma unroll
            for (int i = 0; i < 8; i++) {
                u64 a = pack2(av[i][kk]);
                #pragma unroll
                for (int p = 0; p < 4; p++) acc[i][p] = ffma2(a, w[p], acc[i][p]);
            }
        }
    }
    #pragma unroll
    for (int i = 0; i < 8; i++) {
        int row = r0 + m0 + i;
        if (row < lim) {
            float* dst = g_proj + (size_t)row * PROJW + by * 256 + n0;
            #pragma unroll
            for (int g = 0; g < 2; g++) {
                float2 u0 = unpack2(acc[i][2 * g]);
                float2 u1 = unpack2(acc[i][2 * g + 1]);
                *(float4*)(dst + g * 4) = make_float4(u0.x, u0.y, u1.x, u1.y);
            }
        }
    }
}

// ---------------- fused edge MLP + softmax-free scatter ----------------------
// 256 threads = 8 warps x 32 lanes; tile = 64 edges; 2 blocks/SM.
// Epilogue: attn = exp(logit)/sum (max-free; logits O(1)), each warp scatters
// exp(l)*msg straight from registers via red.global.v4; denom via atomicAdd.
__global__ __launch_bounds__(256, 2) void edge_mlp_kernel(
    const float* __restrict__ edge_feats,
    const float* __restrict__ W1, const float* __restrict__ b1,
    const float* __restrict__ W2, const float* __restrict__ b2,
    const float* __restrict__ w_gate, const float* __restrict__ b_gate,
    const int* __restrict__ senders)
{
    extern __shared__ float smem[];
    float (*s_e)[EPAD] = (float (*)[EPAD])smem;                  // 64 x 36
    float (*s_h)[HPAD] = (float (*)[HPAD])(smem + BM * EPAD);    // 64 x 260
    int* s_is   = (int*)(smem + BM * EPAD + BM * HPAD);
    int* s_ir   = s_is + BM;
    int* s_eidx = s_ir + BM;

    const int cnt = g_count;
    const int e0  = blockIdx.x * BM;
    if (e0 >= cnt) return;
    const int tid = threadIdx.x;

    if (tid < BM) {
        int ci = e0 + tid;
        int e = 0, s = 0, r = 0;
        if (ci < cnt) { e = g_active[ci]; s = senders[e]; r = g_crecv[ci]; }
        s_eidx[tid] = e; s_is[tid] = s; s_ir[tid] = r;
    }
    __syncthreads();

    // pre-sum Ps + Pr into s_h (coalesced, deep load pipeline) + edge feats
    for (int idx = tid; idx < BM * 64; idx += 256) {
        int m = idx >> 6, p = idx & 63;
        const float4 a = *(const float4*)(g_proj + (size_t)s_is[m] * PROJW + p * 4);
        const float4 b = *(const float4*)(g_proj + (size_t)s_ir[m] * PROJW + 256 + p * 4);
        *(float4*)&s_h[m][p * 4] = make_float4(a.x + b.x, a.y + b.y, a.z + b.z, a.w + b.w);
    }
    for (int idx = tid; idx < BM * 8; idx += 256) {
        int m = idx >> 3, p = idx & 7;
        float4 v = make_float4(0.f, 0.f, 0.f, 0.f);
        if (e0 + m < cnt) v = ((const float4*)(edge_feats + (size_t)s_eidx[m] * ED))[p];
        *(float4*)&s_e[m][p * 4] = v;
    }
    __syncthreads();

    const int tx = tid & 31, ty = tid >> 5;
    const int n0 = tx * 8, m0 = ty * 8;

    // ---- GEMM1 (edge part, K=32) + bias: per-thread 8 rows x 8 cols ----
    u64 acc[8][4];
    {
        const u64* bp = (const u64*)(b1 + n0);
        u64 bv[4] = {bp[0], bp[1], bp[2], bp[3]};
        #pragma unroll
        for (int i = 0; i < 8; i++)
            #pragma unroll
            for (int p = 0; p < 4; p++) acc[i][p] = bv[p];
    }
    const float* W1e = W1 + (size_t)(2 * ND) * HID;
    for (int k = 0; k < ED; k += 4) {
        float av[8][4];
        #pragma unroll
        for (int i = 0; i < 8; i++)
            *(float4*)av[i] = *(const float4*)&s_e[m0 + i][k];
        #pragma unroll
        for (int kk = 0; kk < 4; kk++) {
            const ulonglong2* wp = (const ulonglong2*)(W1e + (k + kk) * HID + n0);
            ulonglong2 w01 = wp[0], w23 = wp[1];
            u64 w[4] = {w01.x, w01.y, w23.x, w23.y};
            #pragma unroll
            for (int i = 0; i < 8; i++) {
                u64 a = pack2(av[i][kk]);
                #pragma unroll
                for (int p = 0; p < 4; p++) acc[i][p] = ffma2(a, w[p], acc[i][p]);
            }
        }
    }

    // h = relu(acc + presummed projections) -> s_h
    #pragma unroll
    for (int i = 0; i < 8; i++) {
        int m = m0 + i;
        #pragma unroll
        for (int g = 0; g < 2; g++) {
            float4 hv = *(float4*)&s_h[m][n0 + g * 4];
            float2 u0 = unpack2(acc[i][2 * g]);
            float2 u1 = unpack2(acc[i][2 * g + 1]);
            float4 r;
            r.x = fmaxf(u0.x + hv.x, 0.f);
            r.y = fmaxf(u0.y + hv.y, 0.f);
            r.z = fmaxf(u1.x + hv.z, 0.f);
            r.w = fmaxf(u1.y + hv.w, 0.f);
            *(float4*)&s_h[m][n0 + g * 4] = r;
        }
    }
    __syncthreads();

    // ---- GEMM2: [64x256] @ [256x128]: per-thread 8 rows x 4 cols ----
    const int c0 = tx * 4;
    u64 acc2[8][2];
    {
        const u64* bp = (const u64*)(b2 + c0);
        u64 b0 = bp[0], b1v = bp[1];
        #pragma unroll
        for (int i = 0; i < 8; i++) { acc2[i][0] = b0; acc2[i][1] = b1v; }
    }
    #pragma unroll 2
    for (int k = 0; k < HID; k += 4) {
        float av[8][4];
        #pragma unroll
        for (int i = 0; i < 8; i++)
            *(float4*)av[i] = *(const float4*)&s_h[m0 + i][k];
        #pragma unroll
        for (int kk = 0; kk < 4; kk++) {
            const ulonglong2* wp = (const ulonglong2*)(W2 + (k + kk) * MSGD + c0);
            ulonglong2 w01 = *wp;
            #pragma unroll
            for (int i = 0; i < 8; i++) {
                u64 a = pack2(av[i][kk]);
                acc2[i][0] = ffma2(a, w01.x, acc2[i][0]);
                acc2[i][1] = ffma2(a, w01.y, acc2[i][1]);
            }
        }
    }

    // relu + gate logits (warp reduce) + direct exp-weighted scatter
    float wg[4];
    *(float4*)wg = *(const float4*)(w_gate + c0);
    const float bg = b_gate[0];

    float v0[8], v1[8], v2[8], v3[8], partial[8];
    #pragma unroll
    for (int i = 0; i < 8; i++) {
        float2 u0 = unpack2(acc2[i][0]);
        float2 u1 = unpack2(acc2[i][1]);
        v0[i] = fmaxf(u0.x, 0.f); v1[i] = fmaxf(u0.y, 0.f);
        v2[i] = fmaxf(u1.x, 0.f); v3[i] = fmaxf(u1.y, 0.f);
        float s = v0[i] * wg[0];
        s = fmaf(v1[i], wg[1], s);
        s = fmaf(v2[i], wg[2], s);
        s = fmaf(v3[i], wg[3], s);
        partial[i] = s;
    }
    #pragma unroll
    for (int o = 16; o >= 1; o >>= 1) {
        #pragma unroll
        for (int i = 0; i < 8; i++)
            partial[i] += __shfl_xor_sync(0xffffffffu, partial[i], o);
    }
    #pragma unroll
    for (int i = 0; i < 8; i++) {
        int ci = e0 + m0 + i;
        if (ci < cnt) {
            float ev = expf(partial[i] + bg);        // max-free softmax weight
            int r = s_ir[m0 + i];
            if (tx == 0) atomicAdd(g_denom + r, ev);
            red_add_v4(g_aggr + (size_t)r * MSGD + c0,
                       make_float4(ev * v0[i], ev * v1[i], ev * v2[i], ev * v3[i]));
        }
    }
}

// ---------------- agent MLP (divides by denom on load) -----------------------
__global__ __launch_bounds__(256, 2) void agent_mlp_kernel(
    const float* __restrict__ W_h1, const float* __restrict__ b_h1,
    const float* __restrict__ W_h2, const float* __restrict__ b_h2,
    const float* __restrict__ W_out, const float* __restrict__ b_out,
    float* __restrict__ out, int n_agents)
{
    extern __shared__ float smem[];
    float (*s_x)[XPAD] = (float (*)[XPAD])smem;
    float (*s_h)[HPAD] = (float (*)[HPAD])(smem + BM * XPAD);

    const int r0 = blockIdx.x * BM;
    const int tid = threadIdx.x;

    for (int idx = tid; idx < BM * 32; idx += 256) {
        int m = idx >> 5, p = idx & 31;
        int r = r0 + m;
        float4 v = make_float4(0.f, 0.f, 0.f, 0.f);
        if (r < n_agents) {
            float inv = __frcp_rn(g_denom[r] + 1e-9f);
            v = *(const float4*)(g_aggr + (size_t)r * MSGD + p * 4);
            v.x *= inv; v.y *= inv; v.z *= inv; v.w *= inv;
        }
        *(float4*)&s_x[m][p * 4] = v;
    }
    __syncthreads();

    const int tx = tid & 31, ty = tid >> 5;
    const int n0 = tx * 8, m0 = ty * 8;

    u64 acc[8][4];
    {
        const u64* bp = (const u64*)(b_h1 + n0);
        u64 bv[4] = {bp[0], bp[1], bp[2], bp[3]};
        #pragma unroll
        for (int i = 0; i < 8; i++)
            #pragma unroll
            for (int p = 0; p < 4; p++) acc[i][p] = bv[p];
    }
    for (int k = 0; k < MSGD; k += 4) {
        float av[8][4];
        #pragma unroll
        for (int i = 0; i < 8; i++)
            *(float4*)av[i] = *(const float4*)&s_x[m0 + i][k];
        #pragma unroll
        for (int kk = 0; kk < 4; kk++) {
            const ulonglong2* wp = (const ulonglong2*)(W_h1 + (k + kk) * HID + n0);
            ulonglong2 w01 = wp[0], w23 = wp[1];
            u64 w[4] = {w01.x, w01.y, w23.x, w23.y};
            #pragma unroll
            for (int i = 0; i < 8; i++) {
                u64 a = pack2(av[i][kk]);
                #pragma unroll
                for (int p = 0; p < 4; p++) acc[i][p] = ffma2(a, w[p], acc[i][p]);
            }
        }
    }
    #pragma unroll
    for (int i = 0; i < 8; i++) {
        #pragma unroll
        for (int g = 0; g < 2; g++) {
            float2 u0 = unpack2(acc[i][2 * g]);
            float2 u1 = unpack2(acc[i][2 * g + 1]);
            float4 r;
            r.x = fmaxf(u0.x, 0.f); r.y = fmaxf(u0.y, 0.f);
            r.z = fmaxf(u1.x, 0.f); r.w = fmaxf(u1.y, 0.f);
            *(float4*)&s_h[m0 + i][n0 + g * 4] = r;
        }
    }
    __syncthreads();

    {
        const u64* bp = (const u64*)(b_h2 + n0);
        u64 bv[4] = {bp[0], bp[1], bp[2], bp[3]};
        #pragma unroll
        for (int i = 0; i < 8; i++)
            #pragma unroll
            for (int p = 0; p < 4; p++) acc[i][p] = bv[p];
    }
    #pragma unroll 2
    for (int k = 0; k < HID; k += 4) {
        float av[8][4];
        #pragma unroll
        for (int i = 0; i < 8; i++)
            *(float4*)av[i] = *(const float4*)&s_h[m0 + i][k];
        #pragma unroll
        for (int kk = 0; kk < 4; kk++) {
            const ulonglong2* wp = (const ulonglong2*)(W_h2 + (k + kk) * HID + n0);
            ulonglong2 w01 = wp[0], w23 = wp[1];
            u64 w[4] = {w01.x, w01.y, w23.x, w23.y};
            #pragma unroll
            for (int i = 0; i < 8; i++) {
                u64 a = pack2(av[i][kk]);
                #pragma unroll
                for (int p = 0; p < 4; p++) acc[i][p] = ffma2(a, w[p], acc[i][p]);
            }
        }
    }

    float wo[8];
    *(float4*)&wo[0] = *(const float4*)(W_out + n0);
    *(float4*)&wo[4] = *(const float4*)(W_out + n0 + 4);
    float partial[8];
    #pragma unroll
    for (int i = 0; i < 8; i++) {
        float s = 0.f;
        #pragma unroll
        for (int p = 0; p < 4; p++) {
            float2 u = unpack2(acc[i][p]);
            s = fmaf(fmaxf(u.x, 0.f), wo[2 * p], s);
            s = fmaf(fmaxf(u.y, 0.f), wo[2 * p + 1], s);
        }
        partial[i] = s;
    }
    #pragma unroll
    for (int o = 16; o >= 1; o >>= 1) {
        #pragma unroll
        for (int i = 0; i < 8; i++)
            partial[i] += __shfl_xor_sync(0xffffffffu, partial[i], o);
    }
    if (tx == 0) {
        float bo = b_out[0];
        #pragma unroll
        for (int i = 0; i < 8; i++) {
            int r = r0 + m0 + i;
            if (r < n_agents) out[r] = tanhf(partial[i] + bo);
        }
    }
}

// ---------------------------------------------------------------------------
extern "C" void kernel_launch(void* const* d_in, const int* in_sizes, int n_in,
                              void* d_out, int out_size) {
    const float* node_feats = (const float*)d_in[0];
    const float* edge_feats = (const float*)d_in[1];
    const float* W_msg1 = (const float*)d_in[2];
    const float* b_msg1 = (const float*)d_in[3];
    const float* W_msg2 = (const float*)d_in[4];
    const float* b_msg2 = (const float*)d_in[5];
    const float* w_gate = (const float*)d_in[6];
    const float* b_gate = (const float*)d_in[7];
    const float* W_h1   = (const float*)d_in[8];
    const float* b_h1   = (const float*)d_in[9];
    const float* W_h2   = (const float*)d_in[10];
    const float* b_h2   = (const float*)d_in[11];
    const float* W_out  = (const float*)d_in[12];
    const float* b_out  = (const float*)d_in[13];
    const int* senders   = (const int*)d_in[14];
    const int* receivers = (const int*)d_in[15];
    float* out = (float*)d_out;

    const int n_edges  = in_sizes[14];
    const int n_nodes  = in_sizes[0] / ND;
    const int n_agents = out_size;

    const int SMEM_EDGE  = (BM * EPAD + BM * HPAD) * (int)sizeof(float) + 3 * BM * (int)sizeof(int);
    const int SMEM_AGENT = (BM * XPAD + BM * HPAD) * (int)sizeof(float);
    cudaFuncSetAttribute(edge_mlp_kernel, cudaFuncAttributeMaxDynamicSharedMemorySize, SMEM_EDGE);
    cudaFuncSetAttribute(agent_mlp_kernel, cudaFuncAttributeMaxDynamicSharedMemorySize, SMEM_AGENT);

    {
        int total = n_agents * MSGD;
        init_kernel<<<(total + 255) / 256, 256>>>(n_agents);
    }
    compact_kernel<<<(n_edges + 255) / 256, 256>>>(receivers, n_edges, n_agents);
    {
        dim3 grid((n_nodes + BM - 1) / BM, 2);
        node_proj_kernel<<<grid, 256>>>(node_feats, W_msg1, n_nodes, n_agents);
    }
    {
        int grid = (n_edges + BM - 1) / BM;
        edge_mlp_kernel<<<grid, 256, SMEM_EDGE>>>(
            edge_feats, W_msg1, b_msg1, W_msg2, b_msg2, w_gate, b_gate, senders);
    }
    agent_mlp_kernel<<<(n_agents + BM - 1) / BM, 256, SMEM_AGENT>>>(
        W_h1, b_h1, W_h2, b_h2, W_out, b_out, out, n_agents);
}